// round 14
// baseline (speedup 1.0000x reference)
#include <cuda_runtime.h>
#include <cuda_fp16.h>
#include <cstdint>
#include <math.h>

// Problem constants
#define BATCH   4
#define SEQ     2048
#define DMODEL  1024
#define NHEADS  16
#define DHEAD   64
#define MROWS   (BATCH * SEQ)   // 8192

// -------------------- scratch (device globals; no allocation) --------------------
__device__ __half g_Aq[(size_t)MROWS * DMODEL];
__device__ __half g_Ak[(size_t)MROWS * DMODEL];
__device__ __half g_Av[(size_t)MROWS * DMODEL];
__device__ __half g_Qh[(size_t)MROWS * DMODEL];
__device__ __half g_Kh[(size_t)MROWS * DMODEL];
__device__ __half g_Vh[(size_t)MROWS * DMODEL];
__device__ __half g_Wq[(size_t)DMODEL * DMODEL];
__device__ __half g_Wk[(size_t)DMODEL * DMODEL];
__device__ __half g_Wv[(size_t)DMODEL * DMODEL];
__device__ __half g_Wo[(size_t)DMODEL * DMODEL];

// ==================== PTX helpers (base-sm_103 legal) ====================
__device__ __forceinline__ uint32_t smem_u32(const void* p) {
    uint32_t a;
    asm("{ .reg .u64 t; cvta.to.shared.u64 t, %1; cvt.u32.u64 %0, t; }" : "=r"(a) : "l"(p));
    return a;
}
__device__ __forceinline__ void cpa16(uint32_t s, const void* g) {
    asm volatile("cp.async.cg.shared.global [%0], [%1], 16;" :: "r"(s), "l"(g));
}
__device__ __forceinline__ void cpa_commit() {
    asm volatile("cp.async.commit_group;" ::: "memory");
}
__device__ __forceinline__ void ldsm_x4(uint32_t& r0, uint32_t& r1, uint32_t& r2, uint32_t& r3,
                                        uint32_t addr) {
    asm volatile("ldmatrix.sync.aligned.m8n8.x4.shared.b16 {%0,%1,%2,%3}, [%4];"
                 : "=r"(r0), "=r"(r1), "=r"(r2), "=r"(r3) : "r"(addr));
}
__device__ __forceinline__ void ldsm_x4t(uint32_t& r0, uint32_t& r1, uint32_t& r2, uint32_t& r3,
                                         uint32_t addr) {
    asm volatile("ldmatrix.sync.aligned.m8n8.x4.trans.shared.b16 {%0,%1,%2,%3}, [%4];"
                 : "=r"(r0), "=r"(r1), "=r"(r2), "=r"(r3) : "r"(addr));
}
__device__ __forceinline__ void mma_f16(float* d, const uint32_t* a, const uint32_t* b) {
    asm volatile(
        "mma.sync.aligned.m16n8k16.row.col.f32.f16.f16.f32 "
        "{%0,%1,%2,%3}, {%4,%5,%6,%7}, {%8,%9}, {%0,%1,%2,%3};"
        : "+f"(d[0]), "+f"(d[1]), "+f"(d[2]), "+f"(d[3])
        : "r"(a[0]), "r"(a[1]), "r"(a[2]), "r"(a[3]), "r"(b[0]), "r"(b[1]));
}
__device__ __forceinline__ uint32_t packh2(float hi, float lo) {
    uint32_t r;
    asm("cvt.rn.f16x2.f32 %0, %1, %2;" : "=r"(r) : "f"(hi), "f"(lo));
    return r;
}

// ==================== fused pre-pass: 7x fp32 -> fp16, MLP=8 ====================
#define NACT4 (MROWS * DMODEL / 4)     // 2097152
#define NW4   (DMODEL * DMODEL / 4)    // 262144
#define CONV_BLOCKS 1024
#define CONV_STRIDE (CONV_BLOCKS * 256)  // 262144

struct ConvJobs {
    const float* src[7];
    __half* dst[7];
};

__global__ __launch_bounds__(256)
void conv_all_kernel(ConvJobs jobs) {
    const int z = blockIdx.z;
    const int n4 = (z < 3) ? NACT4 : NW4;
    const float4* __restrict__ src = (const float4*)jobs.src[z];
    uint2* __restrict__ dst = (uint2*)jobs.dst[z];
    int i = blockIdx.x * 256 + threadIdx.x;
#pragma unroll
    for (int it = 0; it < 8; it++) {
        int idx = i + it * CONV_STRIDE;
        if (idx < n4) {
            float4 v = src[idx];
            uint2 r;
            r.x = packh2(v.y, v.x);
            r.y = packh2(v.w, v.z);
            dst[idx] = r;
        }
    }
}

// ==================== single-pass fp16 GEMM (R11 shape: 8 warps, 4Mx2N) ========
// CTA 128x128, BK=64. A K-major (144B rows, non-trans ldsm);
// W native [K,N] (272B rows, ldsm.trans).
#define HBK 64
#define HROWB 144
#define WROWB 272
#define HA_B (128 * HROWB)             // 18432
#define HB_B (HBK * WROWB)             // 17408
#define HSTAGE_B (HA_B + HB_B)         // 35840
#define HGEMM_DYN (2 * HSTAGE_B)       // 71680
#define HNCHUNK (DMODEL / HBK)         // 16

// log2(e)/sqrt(DHEAD): folds softmax scale and exp->exp2 into Q
#define QSCALE 0.18033688011112042f

template <bool F16OUT>
__device__ __forceinline__ void gemm_body(
    const __half* __restrict__ A, const __half* __restrict__ W,
    const float* __restrict__ bias, float outscale,
    __half* __restrict__ Ch, float* __restrict__ Cf, char* smem) {
    const uint32_t sb = smem_u32(smem);
    const int t = threadIdx.x;
    const int lane = t & 31;
    const int wid  = t >> 5;
    const int wm   = wid & 3;
    const int wn   = wid >> 2;
    const int m0 = blockIdx.y * 128;
    const int n0 = blockIdx.x * 128;

    const uint32_t a_off = (uint32_t)((wm * 32 + (lane & 15)) * HROWB + (lane >> 4) * 16);
    const uint32_t b_off = (uint32_t)((lane & 15) * WROWB + ((lane >> 4) & 1) * 16 + wn * 128);

    auto load_stage = [&](int c, int s) {
        const uint32_t st = sb + (uint32_t)s * HSTAGE_B;
        const int k0 = c * HBK;
#pragma unroll
        for (int h = 0; h < 4; h++) {
            int idx = t + h * 256;
            int row = idx >> 3, cc = idx & 7;
            cpa16(st + (uint32_t)(row * HROWB + cc * 16),
                  A + (size_t)(m0 + row) * DMODEL + k0 + cc * 8);
        }
#pragma unroll
        for (int h = 0; h < 4; h++) {
            int idx = t + h * 256;
            int row = idx >> 4, cc = idx & 15;
            cpa16(st + HA_B + (uint32_t)(row * WROWB + cc * 16),
                  W + (size_t)(k0 + row) * DMODEL + n0 + cc * 8);
        }
        cpa_commit();
    };

    float acc[2][8][4];
#pragma unroll
    for (int i = 0; i < 2; i++)
#pragma unroll
        for (int j = 0; j < 8; j++)
#pragma unroll
            for (int r = 0; r < 4; r++) acc[i][j][r] = 0.f;

    load_stage(0, 0);

    for (int c = 0; c < HNCHUNK; c++) {
        if (c + 1 < HNCHUNK) {
            load_stage(c + 1, (c + 1) & 1);
            asm volatile("cp.async.wait_group 1;" ::: "memory");
        } else {
            asm volatile("cp.async.wait_group 0;" ::: "memory");
        }
        __syncthreads();

        const uint32_t st = sb + (uint32_t)(c & 1) * HSTAGE_B;
#pragma unroll
        for (int ks = 0; ks < 4; ks++) {        // 4 x K16 slabs
            uint32_t af[2][4], bf[4][4];
#pragma unroll
            for (int mt = 0; mt < 2; mt++)
                ldsm_x4(af[mt][0], af[mt][1], af[mt][2], af[mt][3],
                        st + a_off + (uint32_t)(mt * 16 * HROWB + ks * 32));
#pragma unroll
            for (int np = 0; np < 4; np++)
                ldsm_x4t(bf[np][0], bf[np][1], bf[np][2], bf[np][3],
                         st + HA_B + b_off + (uint32_t)(ks * 16 * WROWB + np * 32));
#pragma unroll
            for (int mt = 0; mt < 2; mt++)
#pragma unroll
                for (int np = 0; np < 4; np++) {
                    mma_f16(acc[mt][np * 2 + 0], af[mt], &bf[np][0]);
                    mma_f16(acc[mt][np * 2 + 1], af[mt], &bf[np][2]);
                }
        }
        __syncthreads();
    }

    const int gid = lane >> 2, tig = lane & 3;
#pragma unroll
    for (int mt = 0; mt < 2; mt++) {
        const int r0 = m0 + wm * 32 + mt * 16 + gid;
#pragma unroll
        for (int j = 0; j < 8; j++) {
            const int col = n0 + wn * 64 + j * 8 + tig * 2;
            const float bx = bias[col], by = bias[col + 1];
            float v0x = (acc[mt][j][0] + bx) * outscale;
            float v0y = (acc[mt][j][1] + by) * outscale;
            float v1x = (acc[mt][j][2] + bx) * outscale;
            float v1y = (acc[mt][j][3] + by) * outscale;
            if (F16OUT) {
                *(uint32_t*)&Ch[(size_t)r0 * DMODEL + col]       = packh2(v0y, v0x);
                *(uint32_t*)&Ch[(size_t)(r0 + 8) * DMODEL + col] = packh2(v1y, v1x);
            } else {
                float2 a = {v0x, v0y}, b2 = {v1x, v1y};
                *(float2*)&Cf[(size_t)r0 * DMODEL + col]       = a;
                *(float2*)&Cf[(size_t)(r0 + 8) * DMODEL + col] = b2;
            }
        }
    }
}

__global__ __launch_bounds__(256)
void gemm_f16_kernel(const __half* __restrict__ A, const __half* __restrict__ W,
                     const float* __restrict__ bias, float outscale,
                     __half* __restrict__ Ch) {
    extern __shared__ char smem[];
    gemm_body<true>(A, W, bias, outscale, Ch, nullptr, smem);
}

__global__ __launch_bounds__(256)
void gemm_out_kernel(const __half* __restrict__ A, const __half* __restrict__ W,
                     const float* __restrict__ bias, float* __restrict__ Cf) {
    extern __shared__ char smem[];
    gemm_body<false>(A, W, bias, 1.0f, nullptr, Cf, smem);
}

// ==================== flash attention 2 (fp16 mma.sync, BM=128, BN=128, exp2) ====
// CTA: 128 queries, 4 warps; warp owns 32 q-rows = 2 m16 tiles (sequential).
// KV tiles 128x64 fp16 double-buffered; NT=16 halves per-tile fixed costs.
#define FA_BM 128
#define FA_BN 128
#define FA_PADH 72
#define FA_ROWB (FA_PADH * 2)          // 144
#define FA_KV_B (FA_BN * FA_ROWB)      // 18432
#define FA_Q_B  (FA_BM * FA_ROWB)      // 18432
#define FA_DYN  (FA_Q_B + 4 * FA_KV_B) // 92160

__global__ __launch_bounds__(128, 2)
void fa_kernel(const __half* __restrict__ Qh, const __half* __restrict__ Kh,
               const __half* __restrict__ Vh, __half* __restrict__ Oh) {
    extern __shared__ char fsm[];
    const uint32_t sQu = smem_u32(fsm);
    const uint32_t sKu = sQu + FA_Q_B;
    const uint32_t sVu = sKu + 2 * FA_KV_B;
    __half* sQ = (__half*)fsm;

    const int t = threadIdx.x, lane = t & 31, w = t >> 5;
    const int h = blockIdx.y, b = blockIdx.z;
    const size_t qrow0 = (size_t)b * SEQ + (size_t)blockIdx.x * FA_BM;
    const size_t krow0 = (size_t)b * SEQ;
    const int hd = h * DHEAD;

    auto load_kv = [&](int kt, int s) {
#pragma unroll
        for (int i = 0; i < 8; i++) {
            int idx = t + i * 128;
            int r = idx >> 3, c = idx & 7;
            uint32_t so = (uint32_t)(s * FA_KV_B + r * FA_ROWB + c * 16);
            size_t g = (krow0 + (size_t)kt * FA_BN + r) * DMODEL + hd + c * 8;
            cpa16(sKu + so, Kh + g);
            cpa16(sVu + so, Vh + g);
        }
        cpa_commit();
    };

    load_kv(0, 0);
    for (int i = t; i < FA_BM * 8; i += 128) {
        int r = i >> 3, c = i & 7;
        *(uint4*)&sQ[r * FA_PADH + c * 8] =
            *(const uint4*)&Qh[(qrow0 + r) * DMODEL + hd + c * 8];
    }
    __syncthreads();

    // Q a-frags: 2 m-tiles x 4 K16 slabs
    uint32_t qa[2][4][4];
#pragma unroll
    for (int mt = 0; mt < 2; mt++) {
        uint32_t rb = sQu + (uint32_t)((w * 32 + mt * 16 + (lane & 15)) * FA_ROWB
                                       + ((lane >> 4) & 1) * 16);
#pragma unroll
        for (int ks = 0; ks < 4; ks++)
            ldsm_x4(qa[mt][ks][0], qa[mt][ks][1], qa[mt][ks][2], qa[mt][ks][3],
                    rb + ks * 32);
    }

    float oacc[2][8][4];
#pragma unroll
    for (int mt = 0; mt < 2; mt++)
#pragma unroll
        for (int j = 0; j < 8; j++)
#pragma unroll
            for (int r = 0; r < 4; r++) oacc[mt][j][r] = 0.f;
    float mrow[2][2] = {{-1e30f, -1e30f}, {-1e30f, -1e30f}};
    float lrow[2][2] = {{0.f, 0.f}, {0.f, 0.f}};

    const uint32_t k_off = (uint32_t)(((lane & 7) + ((lane >> 4) & 1) * 8) * FA_ROWB
                                      + ((lane >> 3) & 1) * 16);
    const uint32_t v_off = (uint32_t)((lane & 15) * FA_ROWB + ((lane >> 4) & 1) * 16);

    const int NT = SEQ / FA_BN;   // 16
    for (int kt = 0; kt < NT; kt++) {
        if (kt + 1 < NT) {
            load_kv(kt + 1, (kt + 1) & 1);
            asm volatile("cp.async.wait_group 1;" ::: "memory");
        } else {
            asm volatile("cp.async.wait_group 0;" ::: "memory");
        }
        __syncthreads();

        const uint32_t kb_ = sKu + (uint32_t)(kt & 1) * FA_KV_B;
        const uint32_t vb_ = sVu + (uint32_t)(kt & 1) * FA_KV_B;

#pragma unroll
        for (int mt = 0; mt < 2; mt++) {
            // ---- S = Q K^T : 16 n8 tiles (128 keys) ----
            float sacc[16][4];
#pragma unroll
            for (int j = 0; j < 16; j++)
#pragma unroll
                for (int r = 0; r < 4; r++) sacc[j][r] = 0.f;
#pragma unroll
            for (int ks = 0; ks < 4; ks++)
#pragma unroll
                for (int np = 0; np < 8; np++) {
                    uint32_t kb[4];
                    ldsm_x4(kb[0], kb[1], kb[2], kb[3],
                            kb_ + k_off + (uint32_t)(np * 16 * FA_ROWB + ks * 32));
                    mma_f16(sacc[np * 2 + 0], qa[mt][ks], &kb[0]);
                    mma_f16(sacc[np * 2 + 1], qa[mt][ks], &kb[2]);
                }

            // ---- online softmax (base-2) ----
            float mx0 = -1e30f, mx1 = -1e30f;
#pragma unroll
            for (int j = 0; j < 16; j++) {
                mx0 = fmaxf(mx0, fmaxf(sacc[j][0], sacc[j][1]));
                mx1 = fmaxf(mx1, fmaxf(sacc[j][2], sacc[j][3]));
            }
            mx0 = fmaxf(mx0, __shfl_xor_sync(0xFFFFFFFFu, mx0, 1));
            mx0 = fmaxf(mx0, __shfl_xor_sync(0xFFFFFFFFu, mx0, 2));
            mx1 = fmaxf(mx1, __shfl_xor_sync(0xFFFFFFFFu, mx1, 1));
            mx1 = fmaxf(mx1, __shfl_xor_sync(0xFFFFFFFFu, mx1, 2));
            float mn0 = fmaxf(mrow[mt][0], mx0), mn1 = fmaxf(mrow[mt][1], mx1);
            float c0 = exp2f(mrow[mt][0] - mn0), c1 = exp2f(mrow[mt][1] - mn1);
            float rs0 = 0.f, rs1 = 0.f;
#pragma unroll
            for (int j = 0; j < 16; j++) {
                sacc[j][0] = exp2f(sacc[j][0] - mn0);
                sacc[j][1] = exp2f(sacc[j][1] - mn0);
                sacc[j][2] = exp2f(sacc[j][2] - mn1);
                sacc[j][3] = exp2f(sacc[j][3] - mn1);
                rs0 += sacc[j][0] + sacc[j][1];
                rs1 += sacc[j][2] + sacc[j][3];
            }
            rs0 += __shfl_xor_sync(0xFFFFFFFFu, rs0, 1);
            rs0 += __shfl_xor_sync(0xFFFFFFFFu, rs0, 2);
            rs1 += __shfl_xor_sync(0xFFFFFFFFu, rs1, 1);
            rs1 += __shfl_xor_sync(0xFFFFFFFFu, rs1, 2);
            lrow[mt][0] = lrow[mt][0] * c0 + rs0;
            lrow[mt][1] = lrow[mt][1] * c1 + rs1;
            mrow[mt][0] = mn0; mrow[mt][1] = mn1;
#pragma unroll
            for (int j = 0; j < 8; j++) {
                oacc[mt][j][0] *= c0; oacc[mt][j][1] *= c0;
                oacc[mt][j][2] *= c1; oacc[mt][j][3] *= c1;
            }

            // ---- pack P : 8 K16 slabs (128-deep) ----
            uint32_t pa[8][4];
#pragma unroll
            for (int ks = 0; ks < 8; ks++) {
                pa[ks][0] = packh2(sacc[2 * ks][1],     sacc[2 * ks][0]);
                pa[ks][1] = packh2(sacc[2 * ks][3],     sacc[2 * ks][2]);
                pa[ks][2] = packh2(sacc[2 * ks + 1][1], sacc[2 * ks + 1][0]);
                pa[ks][3] = packh2(sacc[2 * ks + 1][3], sacc[2 * ks + 1][2]);
            }

            // ---- O += P V ----
#pragma unroll
            for (int ks = 0; ks < 8; ks++)
#pragma unroll
                for (int np = 0; np < 4; np++) {
                    uint32_t vb[4];
                    ldsm_x4t(vb[0], vb[1], vb[2], vb[3],
                             vb_ + v_off + (uint32_t)(ks * 16 * FA_ROWB + np * 32));
                    mma_f16(oacc[mt][np * 2 + 0], pa[ks], &vb[0]);
                    mma_f16(oacc[mt][np * 2 + 1], pa[ks], &vb[2]);
                }
        }
        __syncthreads();
    }

    // ---- epilogue: normalize, store fp16 ----
#pragma unroll
    for (int mt = 0; mt < 2; mt++) {
        const float il0 = 1.f / lrow[mt][0], il1 = 1.f / lrow[mt][1];
        const size_t r0g = qrow0 + w * 32 + mt * 16 + (lane >> 2);
        const int colb = hd + (lane & 3) * 2;
#pragma unroll
        for (int j = 0; j < 8; j++) {
            const int col = colb + j * 8;
            *(uint32_t*)&Oh[r0g * DMODEL + col] =
                packh2(oacc[mt][j][1] * il0, oacc[mt][j][0] * il0);
            *(uint32_t*)&Oh[(r0g + 8) * DMODEL + col] =
                packh2(oacc[mt][j][3] * il1, oacc[mt][j][2] * il1);
        }
    }
}

// -------------------- launch --------------------
extern "C" void kernel_launch(void* const* d_in, const int* in_sizes, int n_in,
                              void* d_out, int out_size) {
    // metadata order: v, k, q, wq, bq, wk, bk, wv, bv, wo, bo
    const float* v  = (const float*)d_in[0];
    const float* k  = (const float*)d_in[1];
    const float* q  = (const float*)d_in[2];
    const float* wq = (const float*)d_in[3];
    const float* bq = (const float*)d_in[4];
    const float* wk = (const float*)d_in[5];
    const float* bk = (const float*)d_in[6];
    const float* wv = (const float*)d_in[7];
    const float* bv = (const float*)d_in[8];
    const float* wo = (const float*)d_in[9];
    const float* bo = (const float*)d_in[10];
    float* out = (float*)d_out;

    __half *Aq, *Ak, *Av, *Qh, *Kh, *Vh, *Wq, *Wk, *Wv, *Wo;
    cudaGetSymbolAddress((void**)&Aq, g_Aq);
    cudaGetSymbolAddress((void**)&Ak, g_Ak);
    cudaGetSymbolAddress((void**)&Av, g_Av);
    cudaGetSymbolAddress((void**)&Qh, g_Qh);
    cudaGetSymbolAddress((void**)&Kh, g_Kh);
    cudaGetSymbolAddress((void**)&Vh, g_Vh);
    cudaGetSymbolAddress((void**)&Wq, g_Wq);
    cudaGetSymbolAddress((void**)&Wk, g_Wk);
    cudaGetSymbolAddress((void**)&Wv, g_Wv);
    cudaGetSymbolAddress((void**)&Wo, g_Wo);

    cudaFuncSetAttribute(gemm_f16_kernel,
                         cudaFuncAttributeMaxDynamicSharedMemorySize, HGEMM_DYN);
    cudaFuncSetAttribute(gemm_out_kernel,
                         cudaFuncAttributeMaxDynamicSharedMemorySize, HGEMM_DYN);
    cudaFuncSetAttribute(fa_kernel,
                         cudaFuncAttributeMaxDynamicSharedMemorySize, FA_DYN);

    // 1) fused conversions (one launch, MLP=8)
    ConvJobs cj;
    cj.src[0] = q;  cj.dst[0] = Aq;
    cj.src[1] = k;  cj.dst[1] = Ak;
    cj.src[2] = v;  cj.dst[2] = Av;
    cj.src[3] = wq; cj.dst[3] = Wq;
    cj.src[4] = wk; cj.dst[4] = Wk;
    cj.src[5] = wv; cj.dst[5] = Wv;
    cj.src[6] = wo; cj.dst[6] = Wo;
    conv_all_kernel<<<dim3(CONV_BLOCKS, 1, 7), 256>>>(cj);

    // 2) QKV projections (Q folds QSCALE = log2e/8)
    const dim3 ggrid(DMODEL / 128, MROWS / 128);   // (8, 64)
    gemm_f16_kernel<<<ggrid, 256, HGEMM_DYN>>>(Aq, Wq, bq, QSCALE, Qh);
    gemm_f16_kernel<<<ggrid, 256, HGEMM_DYN>>>(Ak, Wk, bk, 1.0f, Kh);
    gemm_f16_kernel<<<ggrid, 256, HGEMM_DYN>>>(Av, Wv, bv, 1.0f, Vh);

    // 3) attention -> fp16 (into Aq, free now)
    fa_kernel<<<dim3(SEQ / FA_BM, NHEADS, BATCH), 128, FA_DYN>>>(Qh, Kh, Vh, Aq);

    // 4) out = O @ wo + bo (fp32)
    gemm_out_kernel<<<ggrid, 256, HGEMM_DYN>>>(Aq, Wo, bo, out);
}

// round 15
// speedup vs baseline: 1.1430x; 1.1430x over previous
#include <cuda_runtime.h>
#include <cuda_fp16.h>
#include <cstdint>
#include <math.h>

// Problem constants
#define BATCH   4
#define SEQ     2048
#define DMODEL  1024
#define NHEADS  16
#define DHEAD   64
#define MROWS   (BATCH * SEQ)   // 8192

// -------------------- scratch (device globals; no allocation) --------------------
__device__ __half g_Aq[(size_t)MROWS * DMODEL];
__device__ __half g_Ak[(size_t)MROWS * DMODEL];
__device__ __half g_Av[(size_t)MROWS * DMODEL];
__device__ __half g_Qh[(size_t)MROWS * DMODEL];
__device__ __half g_Kh[(size_t)MROWS * DMODEL];
__device__ __half g_Vh[(size_t)MROWS * DMODEL];
__device__ __half g_Wq[(size_t)DMODEL * DMODEL];
__device__ __half g_Wk[(size_t)DMODEL * DMODEL];
__device__ __half g_Wv[(size_t)DMODEL * DMODEL];
__device__ __half g_Wo[(size_t)DMODEL * DMODEL];

// ==================== PTX helpers (base-sm_103 legal) ====================
__device__ __forceinline__ uint32_t smem_u32(const void* p) {
    uint32_t a;
    asm("{ .reg .u64 t; cvta.to.shared.u64 t, %1; cvt.u32.u64 %0, t; }" : "=r"(a) : "l"(p));
    return a;
}
__device__ __forceinline__ void cpa16(uint32_t s, const void* g) {
    asm volatile("cp.async.cg.shared.global [%0], [%1], 16;" :: "r"(s), "l"(g));
}
__device__ __forceinline__ void cpa_commit() {
    asm volatile("cp.async.commit_group;" ::: "memory");
}
__device__ __forceinline__ void ldsm_x4(uint32_t& r0, uint32_t& r1, uint32_t& r2, uint32_t& r3,
                                        uint32_t addr) {
    asm volatile("ldmatrix.sync.aligned.m8n8.x4.shared.b16 {%0,%1,%2,%3}, [%4];"
                 : "=r"(r0), "=r"(r1), "=r"(r2), "=r"(r3) : "r"(addr));
}
__device__ __forceinline__ void ldsm_x4t(uint32_t& r0, uint32_t& r1, uint32_t& r2, uint32_t& r3,
                                         uint32_t addr) {
    asm volatile("ldmatrix.sync.aligned.m8n8.x4.trans.shared.b16 {%0,%1,%2,%3}, [%4];"
                 : "=r"(r0), "=r"(r1), "=r"(r2), "=r"(r3) : "r"(addr));
}
__device__ __forceinline__ void mma_f16(float* d, const uint32_t* a, const uint32_t* b) {
    asm volatile(
        "mma.sync.aligned.m16n8k16.row.col.f32.f16.f16.f32 "
        "{%0,%1,%2,%3}, {%4,%5,%6,%7}, {%8,%9}, {%0,%1,%2,%3};"
        : "+f"(d[0]), "+f"(d[1]), "+f"(d[2]), "+f"(d[3])
        : "r"(a[0]), "r"(a[1]), "r"(a[2]), "r"(a[3]), "r"(b[0]), "r"(b[1]));
}
__device__ __forceinline__ uint32_t packh2(float hi, float lo) {
    uint32_t r;
    asm("cvt.rn.f16x2.f32 %0, %1, %2;" : "=r"(r) : "f"(hi), "f"(lo));
    return r;
}

// ==================== fused pre-pass: 7x fp32 -> fp16, MLP=4 ====================
#define NACT4 (MROWS * DMODEL / 4)     // 2097152
#define NW4   (DMODEL * DMODEL / 4)    // 262144
#define CONV_BLOCKS 2048
#define CONV_STRIDE (CONV_BLOCKS * 256)

struct ConvJobs {
    const float* src[7];
    __half* dst[7];
};

__global__ __launch_bounds__(256)
void conv_all_kernel(ConvJobs jobs) {
    const int z = blockIdx.z;
    const int n4 = (z < 3) ? NACT4 : NW4;
    const float4* __restrict__ src = (const float4*)jobs.src[z];
    uint2* __restrict__ dst = (uint2*)jobs.dst[z];
    int i = blockIdx.x * 256 + threadIdx.x;
#pragma unroll
    for (int it = 0; it < 4; it++) {
        int idx = i + it * CONV_STRIDE;
        if (idx < n4) {
            float4 v = src[idx];
            uint2 r;
            r.x = packh2(v.y, v.x);
            r.y = packh2(v.w, v.z);
            dst[idx] = r;
        }
    }
}

// ==================== single-pass fp16 GEMM, 3-stage cp.async pipeline =========
// CTA 128x128, BK=64, 8 warps (4M x 2N). A K-major (144B rows, non-trans ldsm);
// W native [K,N] (272B rows, ldsm.trans). One __syncthreads per chunk.
#define HBK 64
#define HROWB 144
#define WROWB 272
#define HA_B (128 * HROWB)             // 18432
#define HB_B (HBK * WROWB)             // 17408
#define HSTAGE_B (HA_B + HB_B)         // 35840
#define HSTAGES 3
#define HGEMM_DYN (HSTAGES * HSTAGE_B) // 107520
#define HNCHUNK (DMODEL / HBK)         // 16

// log2(e)/sqrt(DHEAD): folds softmax scale and exp->exp2 into Q
#define QSCALE 0.18033688011112042f

template <bool F16OUT>
__device__ __forceinline__ void gemm_body(
    const __half* __restrict__ A, const __half* __restrict__ W,
    const float* __restrict__ bias, float outscale,
    __half* __restrict__ Ch, float* __restrict__ Cf, char* smem) {
    const uint32_t sb = smem_u32(smem);
    const int t = threadIdx.x;
    const int lane = t & 31;
    const int wid  = t >> 5;
    const int wm   = wid & 3;
    const int wn   = wid >> 2;
    const int m0 = blockIdx.y * 128;
    const int n0 = blockIdx.x * 128;

    const uint32_t a_off = (uint32_t)((wm * 32 + (lane & 15)) * HROWB + (lane >> 4) * 16);
    const uint32_t b_off = (uint32_t)((lane & 15) * WROWB + ((lane >> 4) & 1) * 16 + wn * 128);

    auto load_stage = [&](int c, int s) {
        const uint32_t st = sb + (uint32_t)s * HSTAGE_B;
        const int k0 = c * HBK;
#pragma unroll
        for (int h = 0; h < 4; h++) {
            int idx = t + h * 256;
            int row = idx >> 3, cc = idx & 7;
            cpa16(st + (uint32_t)(row * HROWB + cc * 16),
                  A + (size_t)(m0 + row) * DMODEL + k0 + cc * 8);
        }
#pragma unroll
        for (int h = 0; h < 4; h++) {
            int idx = t + h * 256;
            int row = idx >> 4, cc = idx & 15;
            cpa16(st + HA_B + (uint32_t)(row * WROWB + cc * 16),
                  W + (size_t)(k0 + row) * DMODEL + n0 + cc * 8);
        }
        cpa_commit();
    };

    float acc[2][8][4];
#pragma unroll
    for (int i = 0; i < 2; i++)
#pragma unroll
        for (int j = 0; j < 8; j++)
#pragma unroll
            for (int r = 0; r < 4; r++) acc[i][j][r] = 0.f;

    // prologue: 2 stages in flight
    load_stage(0, 0);
    load_stage(1, 1);

    int slot = 0;
#pragma unroll 1
    for (int c = 0; c < HNCHUNK; c++) {
        if (c < HNCHUNK - 1) {
            asm volatile("cp.async.wait_group 1;" ::: "memory");
        } else {
            asm volatile("cp.async.wait_group 0;" ::: "memory");
        }
        __syncthreads();   // stage c visible to all; slot (c-1) fully consumed

        if (c + 2 < HNCHUNK) {
            int ns = slot + 2; if (ns >= HSTAGES) ns -= HSTAGES;
            load_stage(c + 2, ns);
        }

        const uint32_t st = sb + (uint32_t)slot * HSTAGE_B;
#pragma unroll
        for (int ks = 0; ks < 4; ks++) {        // 4 x K16 slabs
            uint32_t af[2][4], bf[4][4];
#pragma unroll
            for (int mt = 0; mt < 2; mt++)
                ldsm_x4(af[mt][0], af[mt][1], af[mt][2], af[mt][3],
                        st + a_off + (uint32_t)(mt * 16 * HROWB + ks * 32));
#pragma unroll
            for (int np = 0; np < 4; np++)
                ldsm_x4t(bf[np][0], bf[np][1], bf[np][2], bf[np][3],
                         st + HA_B + b_off + (uint32_t)(ks * 16 * WROWB + np * 32));
#pragma unroll
            for (int mt = 0; mt < 2; mt++)
#pragma unroll
                for (int np = 0; np < 4; np++) {
                    mma_f16(acc[mt][np * 2 + 0], af[mt], &bf[np][0]);
                    mma_f16(acc[mt][np * 2 + 1], af[mt], &bf[np][2]);
                }
        }
        if (++slot == HSTAGES) slot = 0;
    }

    const int gid = lane >> 2, tig = lane & 3;
#pragma unroll
    for (int mt = 0; mt < 2; mt++) {
        const int r0 = m0 + wm * 32 + mt * 16 + gid;
#pragma unroll
        for (int j = 0; j < 8; j++) {
            const int col = n0 + wn * 64 + j * 8 + tig * 2;
            const float bx = bias[col], by = bias[col + 1];
            float v0x = (acc[mt][j][0] + bx) * outscale;
            float v0y = (acc[mt][j][1] + by) * outscale;
            float v1x = (acc[mt][j][2] + bx) * outscale;
            float v1y = (acc[mt][j][3] + by) * outscale;
            if (F16OUT) {
                *(uint32_t*)&Ch[(size_t)r0 * DMODEL + col]       = packh2(v0y, v0x);
                *(uint32_t*)&Ch[(size_t)(r0 + 8) * DMODEL + col] = packh2(v1y, v1x);
            } else {
                float2 a = {v0x, v0y}, b2 = {v1x, v1y};
                *(float2*)&Cf[(size_t)r0 * DMODEL + col]       = a;
                *(float2*)&Cf[(size_t)(r0 + 8) * DMODEL + col] = b2;
            }
        }
    }
}

__global__ __launch_bounds__(256)
void gemm_f16_kernel(const __half* __restrict__ A, const __half* __restrict__ W,
                     const float* __restrict__ bias, float outscale,
                     __half* __restrict__ Ch) {
    extern __shared__ char smem[];
    gemm_body<true>(A, W, bias, outscale, Ch, nullptr, smem);
}

__global__ __launch_bounds__(256)
void gemm_out_kernel(const __half* __restrict__ A, const __half* __restrict__ W,
                     const float* __restrict__ bias, float* __restrict__ Cf) {
    extern __shared__ char smem[];
    gemm_body<false>(A, W, bias, 1.0f, nullptr, Cf, smem);
}

// ==================== flash attention 2 (fp16 mma.sync, BM=128, BN=64, exp2) =====
// R11 configuration verbatim (BN=128 regressed: register blowup).
#define FA_BM 128
#define FA_BN 64
#define FA_PADH 72
#define FA_ROWB (FA_PADH * 2)          // 144
#define FA_KV_B (FA_BN * FA_ROWB)      // 9216
#define FA_Q_B  (FA_BM * FA_ROWB)      // 18432
#define FA_DYN  (FA_Q_B + 4 * FA_KV_B) // 55296

__global__ __launch_bounds__(128, 2)
void fa_kernel(const __half* __restrict__ Qh, const __half* __restrict__ Kh,
               const __half* __restrict__ Vh, __half* __restrict__ Oh) {
    extern __shared__ char fsm[];
    const uint32_t sQu = smem_u32(fsm);
    const uint32_t sKu = sQu + FA_Q_B;
    const uint32_t sVu = sKu + 2 * FA_KV_B;
    __half* sQ = (__half*)fsm;

    const int t = threadIdx.x, lane = t & 31, w = t >> 5;
    const int h = blockIdx.y, b = blockIdx.z;
    const size_t qrow0 = (size_t)b * SEQ + (size_t)blockIdx.x * FA_BM;
    const size_t krow0 = (size_t)b * SEQ;
    const int hd = h * DHEAD;

    auto load_kv = [&](int kt, int s) {
#pragma unroll
        for (int i = 0; i < 4; i++) {
            int idx = t + i * 128;
            int r = idx >> 3, c = idx & 7;
            uint32_t so = (uint32_t)(s * FA_KV_B + r * FA_ROWB + c * 16);
            size_t g = (krow0 + (size_t)kt * FA_BN + r) * DMODEL + hd + c * 8;
            cpa16(sKu + so, Kh + g);
            cpa16(sVu + so, Vh + g);
        }
        cpa_commit();
    };

    load_kv(0, 0);
    for (int i = t; i < FA_BM * 8; i += 128) {
        int r = i >> 3, c = i & 7;
        *(uint4*)&sQ[r * FA_PADH + c * 8] =
            *(const uint4*)&Qh[(qrow0 + r) * DMODEL + hd + c * 8];
    }
    __syncthreads();

    uint32_t qa[2][4][4];
#pragma unroll
    for (int mt = 0; mt < 2; mt++) {
        uint32_t rb = sQu + (uint32_t)((w * 32 + mt * 16 + (lane & 15)) * FA_ROWB
                                       + ((lane >> 4) & 1) * 16);
#pragma unroll
        for (int ks = 0; ks < 4; ks++)
            ldsm_x4(qa[mt][ks][0], qa[mt][ks][1], qa[mt][ks][2], qa[mt][ks][3],
                    rb + ks * 32);
    }

    float oacc[2][8][4];
#pragma unroll
    for (int mt = 0; mt < 2; mt++)
#pragma unroll
        for (int j = 0; j < 8; j++)
#pragma unroll
            for (int r = 0; r < 4; r++) oacc[mt][j][r] = 0.f;
    float mrow[2][2] = {{-1e30f, -1e30f}, {-1e30f, -1e30f}};
    float lrow[2][2] = {{0.f, 0.f}, {0.f, 0.f}};

    const uint32_t k_off = (uint32_t)(((lane & 7) + ((lane >> 4) & 1) * 8) * FA_ROWB
                                      + ((lane >> 3) & 1) * 16);
    const uint32_t v_off = (uint32_t)((lane & 15) * FA_ROWB + ((lane >> 4) & 1) * 16);

    const int NT = SEQ / FA_BN;   // 32
    for (int kt = 0; kt < NT; kt++) {
        if (kt + 1 < NT) {
            load_kv(kt + 1, (kt + 1) & 1);
            asm volatile("cp.async.wait_group 1;" ::: "memory");
        } else {
            asm volatile("cp.async.wait_group 0;" ::: "memory");
        }
        __syncthreads();

        const uint32_t kb_ = sKu + (uint32_t)(kt & 1) * FA_KV_B;
        const uint32_t vb_ = sVu + (uint32_t)(kt & 1) * FA_KV_B;

#pragma unroll
        for (int mt = 0; mt < 2; mt++) {
            // ---- S = Q K^T (log2e * scale pre-folded into Q) ----
            float sacc[8][4];
#pragma unroll
            for (int j = 0; j < 8; j++)
#pragma unroll
                for (int r = 0; r < 4; r++) sacc[j][r] = 0.f;
#pragma unroll
            for (int ks = 0; ks < 4; ks++)
#pragma unroll
                for (int np = 0; np < 4; np++) {
                    uint32_t kb[4];
                    ldsm_x4(kb[0], kb[1], kb[2], kb[3],
                            kb_ + k_off + (uint32_t)(np * 16 * FA_ROWB + ks * 32));
                    mma_f16(sacc[np * 2 + 0], qa[mt][ks], &kb[0]);
                    mma_f16(sacc[np * 2 + 1], qa[mt][ks], &kb[2]);
                }

            // ---- online softmax (base-2) ----
            float mx0 = -1e30f, mx1 = -1e30f;
#pragma unroll
            for (int j = 0; j < 8; j++) {
                mx0 = fmaxf(mx0, fmaxf(sacc[j][0], sacc[j][1]));
                mx1 = fmaxf(mx1, fmaxf(sacc[j][2], sacc[j][3]));
            }
            mx0 = fmaxf(mx0, __shfl_xor_sync(0xFFFFFFFFu, mx0, 1));
            mx0 = fmaxf(mx0, __shfl_xor_sync(0xFFFFFFFFu, mx0, 2));
            mx1 = fmaxf(mx1, __shfl_xor_sync(0xFFFFFFFFu, mx1, 1));
            mx1 = fmaxf(mx1, __shfl_xor_sync(0xFFFFFFFFu, mx1, 2));
            float mn0 = fmaxf(mrow[mt][0], mx0), mn1 = fmaxf(mrow[mt][1], mx1);
            float c0 = exp2f(mrow[mt][0] - mn0), c1 = exp2f(mrow[mt][1] - mn1);
            float rs0 = 0.f, rs1 = 0.f;
#pragma unroll
            for (int j = 0; j < 8; j++) {
                sacc[j][0] = exp2f(sacc[j][0] - mn0);
                sacc[j][1] = exp2f(sacc[j][1] - mn0);
                sacc[j][2] = exp2f(sacc[j][2] - mn1);
                sacc[j][3] = exp2f(sacc[j][3] - mn1);
                rs0 += sacc[j][0] + sacc[j][1];
                rs1 += sacc[j][2] + sacc[j][3];
            }
            rs0 += __shfl_xor_sync(0xFFFFFFFFu, rs0, 1);
            rs0 += __shfl_xor_sync(0xFFFFFFFFu, rs0, 2);
            rs1 += __shfl_xor_sync(0xFFFFFFFFu, rs1, 1);
            rs1 += __shfl_xor_sync(0xFFFFFFFFu, rs1, 2);
            lrow[mt][0] = lrow[mt][0] * c0 + rs0;
            lrow[mt][1] = lrow[mt][1] * c1 + rs1;
            mrow[mt][0] = mn0; mrow[mt][1] = mn1;
#pragma unroll
            for (int j = 0; j < 8; j++) {
                oacc[mt][j][0] *= c0; oacc[mt][j][1] *= c0;
                oacc[mt][j][2] *= c1; oacc[mt][j][3] *= c1;
            }

            // ---- pack P ----
            uint32_t pa[4][4];
#pragma unroll
            for (int ks = 0; ks < 4; ks++) {
                pa[ks][0] = packh2(sacc[2 * ks][1],     sacc[2 * ks][0]);
                pa[ks][1] = packh2(sacc[2 * ks][3],     sacc[2 * ks][2]);
                pa[ks][2] = packh2(sacc[2 * ks + 1][1], sacc[2 * ks + 1][0]);
                pa[ks][3] = packh2(sacc[2 * ks + 1][3], sacc[2 * ks + 1][2]);
            }

            // ---- O += P V ----
#pragma unroll
            for (int ks = 0; ks < 4; ks++)
#pragma unroll
                for (int np = 0; np < 4; np++) {
                    uint32_t vb[4];
                    ldsm_x4t(vb[0], vb[1], vb[2], vb[3],
                             vb_ + v_off + (uint32_t)(ks * 16 * FA_ROWB + np * 32));
                    mma_f16(oacc[mt][np * 2 + 0], pa[ks], &vb[0]);
                    mma_f16(oacc[mt][np * 2 + 1], pa[ks], &vb[2]);
                }
        }
        __syncthreads();
    }

    // ---- epilogue: normalize, store fp16 ----
#pragma unroll
    for (int mt = 0; mt < 2; mt++) {
        const float il0 = 1.f / lrow[mt][0], il1 = 1.f / lrow[mt][1];
        const size_t r0g = qrow0 + w * 32 + mt * 16 + (lane >> 2);
        const int colb = hd + (lane & 3) * 2;
#pragma unroll
        for (int j = 0; j < 8; j++) {
            const int col = colb + j * 8;
            *(uint32_t*)&Oh[r0g * DMODEL + col] =
                packh2(oacc[mt][j][1] * il0, oacc[mt][j][0] * il0);
            *(uint32_t*)&Oh[(r0g + 8) * DMODEL + col] =
                packh2(oacc[mt][j][3] * il1, oacc[mt][j][2] * il1);
        }
    }
}

// -------------------- launch --------------------
extern "C" void kernel_launch(void* const* d_in, const int* in_sizes, int n_in,
                              void* d_out, int out_size) {
    // metadata order: v, k, q, wq, bq, wk, bk, wv, bv, wo, bo
    const float* v  = (const float*)d_in[0];
    const float* k  = (const float*)d_in[1];
    const float* q  = (const float*)d_in[2];
    const float* wq = (const float*)d_in[3];
    const float* bq = (const float*)d_in[4];
    const float* wk = (const float*)d_in[5];
    const float* bk = (const float*)d_in[6];
    const float* wv = (const float*)d_in[7];
    const float* bv = (const float*)d_in[8];
    const float* wo = (const float*)d_in[9];
    const float* bo = (const float*)d_in[10];
    float* out = (float*)d_out;

    __half *Aq, *Ak, *Av, *Qh, *Kh, *Vh, *Wq, *Wk, *Wv, *Wo;
    cudaGetSymbolAddress((void**)&Aq, g_Aq);
    cudaGetSymbolAddress((void**)&Ak, g_Ak);
    cudaGetSymbolAddress((void**)&Av, g_Av);
    cudaGetSymbolAddress((void**)&Qh, g_Qh);
    cudaGetSymbolAddress((void**)&Kh, g_Kh);
    cudaGetSymbolAddress((void**)&Vh, g_Vh);
    cudaGetSymbolAddress((void**)&Wq, g_Wq);
    cudaGetSymbolAddress((void**)&Wk, g_Wk);
    cudaGetSymbolAddress((void**)&Wv, g_Wv);
    cudaGetSymbolAddress((void**)&Wo, g_Wo);

    cudaFuncSetAttribute(gemm_f16_kernel,
                         cudaFuncAttributeMaxDynamicSharedMemorySize, HGEMM_DYN);
    cudaFuncSetAttribute(gemm_out_kernel,
                         cudaFuncAttributeMaxDynamicSharedMemorySize, HGEMM_DYN);
    cudaFuncSetAttribute(fa_kernel,
                         cudaFuncAttributeMaxDynamicSharedMemorySize, FA_DYN);

    // 1) fused conversions (one launch, MLP=4)
    ConvJobs cj;
    cj.src[0] = q;  cj.dst[0] = Aq;
    cj.src[1] = k;  cj.dst[1] = Ak;
    cj.src[2] = v;  cj.dst[2] = Av;
    cj.src[3] = wq; cj.dst[3] = Wq;
    cj.src[4] = wk; cj.dst[4] = Wk;
    cj.src[5] = wv; cj.dst[5] = Wv;
    cj.src[6] = wo; cj.dst[6] = Wo;
    conv_all_kernel<<<dim3(CONV_BLOCKS, 1, 7), 256>>>(cj);

    // 2) QKV projections (Q folds QSCALE = log2e/8)
    const dim3 ggrid(DMODEL / 128, MROWS / 128);   // (8, 64)
    gemm_f16_kernel<<<ggrid, 256, HGEMM_DYN>>>(Aq, Wq, bq, QSCALE, Qh);
    gemm_f16_kernel<<<ggrid, 256, HGEMM_DYN>>>(Ak, Wk, bk, 1.0f, Kh);
    gemm_f16_kernel<<<ggrid, 256, HGEMM_DYN>>>(Av, Wv, bv, 1.0f, Vh);

    // 3) attention -> fp16 (into Aq, free now)
    fa_kernel<<<dim3(SEQ / FA_BM, NHEADS, BATCH), 128, FA_DYN>>>(Qh, Kh, Vh, Aq);

    // 4) out = O @ wo + bo (fp32)
    gemm_out_kernel<<<ggrid, 256, HGEMM_DYN>>>(Aq, Wo, bo, out);
}

// round 16
// speedup vs baseline: 1.1986x; 1.0487x over previous
#include <cuda_runtime.h>
#include <cuda_fp16.h>
#include <cstdint>
#include <math.h>

// Problem constants
#define BATCH   4
#define SEQ     2048
#define DMODEL  1024
#define NHEADS  16
#define DHEAD   64
#define MROWS   (BATCH * SEQ)   // 8192

// -------------------- scratch (device globals; no allocation) --------------------
__device__ __half g_Aq[(size_t)MROWS * DMODEL];
__device__ __half g_Ak[(size_t)MROWS * DMODEL];
__device__ __half g_Av[(size_t)MROWS * DMODEL];
__device__ __half g_Qh[(size_t)MROWS * DMODEL];
__device__ __half g_Kh[(size_t)MROWS * DMODEL];
__device__ __half g_Vh[(size_t)MROWS * DMODEL];
__device__ __half g_Wq[(size_t)DMODEL * DMODEL];
__device__ __half g_Wk[(size_t)DMODEL * DMODEL];
__device__ __half g_Wv[(size_t)DMODEL * DMODEL];
__device__ __half g_Wo[(size_t)DMODEL * DMODEL];

// ==================== PTX helpers (base-sm_103 legal) ====================
__device__ __forceinline__ uint32_t smem_u32(const void* p) {
    uint32_t a;
    asm("{ .reg .u64 t; cvta.to.shared.u64 t, %1; cvt.u32.u64 %0, t; }" : "=r"(a) : "l"(p));
    return a;
}
__device__ __forceinline__ void cpa16(uint32_t s, const void* g) {
    asm volatile("cp.async.cg.shared.global [%0], [%1], 16;" :: "r"(s), "l"(g));
}
__device__ __forceinline__ void cpa_commit() {
    asm volatile("cp.async.commit_group;" ::: "memory");
}
__device__ __forceinline__ void ldsm_x4(uint32_t& r0, uint32_t& r1, uint32_t& r2, uint32_t& r3,
                                        uint32_t addr) {
    asm volatile("ldmatrix.sync.aligned.m8n8.x4.shared.b16 {%0,%1,%2,%3}, [%4];"
                 : "=r"(r0), "=r"(r1), "=r"(r2), "=r"(r3) : "r"(addr));
}
__device__ __forceinline__ void ldsm_x4t(uint32_t& r0, uint32_t& r1, uint32_t& r2, uint32_t& r3,
                                         uint32_t addr) {
    asm volatile("ldmatrix.sync.aligned.m8n8.x4.trans.shared.b16 {%0,%1,%2,%3}, [%4];"
                 : "=r"(r0), "=r"(r1), "=r"(r2), "=r"(r3) : "r"(addr));
}
__device__ __forceinline__ void mma_f16(float* d, const uint32_t* a, const uint32_t* b) {
    asm volatile(
        "mma.sync.aligned.m16n8k16.row.col.f32.f16.f16.f32 "
        "{%0,%1,%2,%3}, {%4,%5,%6,%7}, {%8,%9}, {%0,%1,%2,%3};"
        : "+f"(d[0]), "+f"(d[1]), "+f"(d[2]), "+f"(d[3])
        : "r"(a[0]), "r"(a[1]), "r"(a[2]), "r"(a[3]), "r"(b[0]), "r"(b[1]));
}
__device__ __forceinline__ uint32_t packh2(float hi, float lo) {
    uint32_t r;
    asm("cvt.rn.f16x2.f32 %0, %1, %2;" : "=r"(r) : "f"(hi), "f"(lo));
    return r;
}

// ==================== pre-pass: fp32 -> fp16 (layout-preserving) ====================
__global__ __launch_bounds__(256)
void conv_f16_kernel(const float* __restrict__ in, __half* __restrict__ out, int n4) {
    int i = blockIdx.x * blockDim.x + threadIdx.x;
    if (i >= n4) return;
    float4 v = ((const float4*)in)[i];
    uint2 r;
    r.x = packh2(v.y, v.x);
    r.y = packh2(v.w, v.z);
    ((uint2*)out)[i] = r;
}

// ==================== single-pass fp16 GEMM, 3-stage cp.async pipeline =========
// CTA 128x128, BK=64, 8 warps (4M x 2N). A K-major (144B rows, non-trans ldsm);
// W native [K,N] (272B rows, ldsm.trans). One __syncthreads per chunk.
#define HBK 64
#define HROWB 144
#define WROWB 272
#define HA_B (128 * HROWB)             // 18432
#define HB_B (HBK * WROWB)             // 17408
#define HSTAGE_B (HA_B + HB_B)         // 35840
#define HSTAGES 3
#define HGEMM_DYN (HSTAGES * HSTAGE_B) // 107520
#define HNCHUNK (DMODEL / HBK)         // 16

// log2(e)/sqrt(DHEAD): folds softmax scale and exp->exp2 into Q
#define QSCALE 0.18033688011112042f

template <bool F16OUT>
__device__ __forceinline__ void gemm_body(
    const __half* __restrict__ A, const __half* __restrict__ W,
    const float* __restrict__ bias, float outscale,
    __half* __restrict__ Ch, float* __restrict__ Cf, char* smem) {
    const uint32_t sb = smem_u32(smem);
    const int t = threadIdx.x;
    const int lane = t & 31;
    const int wid  = t >> 5;
    const int wm   = wid & 3;
    const int wn   = wid >> 2;
    const int m0 = blockIdx.y * 128;
    const int n0 = blockIdx.x * 128;

    const uint32_t a_off = (uint32_t)((wm * 32 + (lane & 15)) * HROWB + (lane >> 4) * 16);
    const uint32_t b_off = (uint32_t)((lane & 15) * WROWB + ((lane >> 4) & 1) * 16 + wn * 128);

    auto load_stage = [&](int c, int s) {
        const uint32_t st = sb + (uint32_t)s * HSTAGE_B;
        const int k0 = c * HBK;
#pragma unroll
        for (int h = 0; h < 4; h++) {
            int idx = t + h * 256;
            int row = idx >> 3, cc = idx & 7;
            cpa16(st + (uint32_t)(row * HROWB + cc * 16),
                  A + (size_t)(m0 + row) * DMODEL + k0 + cc * 8);
        }
#pragma unroll
        for (int h = 0; h < 4; h++) {
            int idx = t + h * 256;
            int row = idx >> 4, cc = idx & 15;
            cpa16(st + HA_B + (uint32_t)(row * WROWB + cc * 16),
                  W + (size_t)(k0 + row) * DMODEL + n0 + cc * 8);
        }
        cpa_commit();
    };

    float acc[2][8][4];
#pragma unroll
    for (int i = 0; i < 2; i++)
#pragma unroll
        for (int j = 0; j < 8; j++)
#pragma unroll
            for (int r = 0; r < 4; r++) acc[i][j][r] = 0.f;

    // prologue: 2 stages in flight
    load_stage(0, 0);
    load_stage(1, 1);

    int slot = 0;
#pragma unroll 1
    for (int c = 0; c < HNCHUNK; c++) {
        if (c < HNCHUNK - 1) {
            asm volatile("cp.async.wait_group 1;" ::: "memory");
        } else {
            asm volatile("cp.async.wait_group 0;" ::: "memory");
        }
        __syncthreads();   // stage c visible to all; slot (c-1) fully consumed

        if (c + 2 < HNCHUNK) {
            int ns = slot + 2; if (ns >= HSTAGES) ns -= HSTAGES;
            load_stage(c + 2, ns);
        }

        const uint32_t st = sb + (uint32_t)slot * HSTAGE_B;
#pragma unroll
        for (int ks = 0; ks < 4; ks++) {        // 4 x K16 slabs
            uint32_t af[2][4], bf[4][4];
#pragma unroll
            for (int mt = 0; mt < 2; mt++)
                ldsm_x4(af[mt][0], af[mt][1], af[mt][2], af[mt][3],
                        st + a_off + (uint32_t)(mt * 16 * HROWB + ks * 32));
#pragma unroll
            for (int np = 0; np < 4; np++)
                ldsm_x4t(bf[np][0], bf[np][1], bf[np][2], bf[np][3],
                         st + HA_B + b_off + (uint32_t)(ks * 16 * WROWB + np * 32));
#pragma unroll
            for (int mt = 0; mt < 2; mt++)
#pragma unroll
                for (int np = 0; np < 4; np++) {
                    mma_f16(acc[mt][np * 2 + 0], af[mt], &bf[np][0]);
                    mma_f16(acc[mt][np * 2 + 1], af[mt], &bf[np][2]);
                }
        }
        if (++slot == HSTAGES) slot = 0;
    }

    const int gid = lane >> 2, tig = lane & 3;
#pragma unroll
    for (int mt = 0; mt < 2; mt++) {
        const int r0 = m0 + wm * 32 + mt * 16 + gid;
#pragma unroll
        for (int j = 0; j < 8; j++) {
            const int col = n0 + wn * 64 + j * 8 + tig * 2;
            const float bx = bias[col], by = bias[col + 1];
            float v0x = (acc[mt][j][0] + bx) * outscale;
            float v0y = (acc[mt][j][1] + by) * outscale;
            float v1x = (acc[mt][j][2] + bx) * outscale;
            float v1y = (acc[mt][j][3] + by) * outscale;
            if (F16OUT) {
                *(uint32_t*)&Ch[(size_t)r0 * DMODEL + col]       = packh2(v0y, v0x);
                *(uint32_t*)&Ch[(size_t)(r0 + 8) * DMODEL + col] = packh2(v1y, v1x);
            } else {
                float2 a = {v0x, v0y}, b2 = {v1x, v1y};
                *(float2*)&Cf[(size_t)r0 * DMODEL + col]       = a;
                *(float2*)&Cf[(size_t)(r0 + 8) * DMODEL + col] = b2;
            }
        }
    }
}

__global__ __launch_bounds__(256)
void gemm_f16_kernel(const __half* __restrict__ A, const __half* __restrict__ W,
                     const float* __restrict__ bias, float outscale,
                     __half* __restrict__ Ch) {
    extern __shared__ char smem[];
    gemm_body<true>(A, W, bias, outscale, Ch, nullptr, smem);
}

__global__ __launch_bounds__(256)
void gemm_out_kernel(const __half* __restrict__ A, const __half* __restrict__ W,
                     const float* __restrict__ bias, float* __restrict__ Cf) {
    extern __shared__ char smem[];
    gemm_body<false>(A, W, bias, 1.0f, nullptr, Cf, smem);
}

// ==================== flash attention 2 (fp16 mma.sync, BM=128, BN=64, exp2) =====
// R11 configuration, but single __syncthreads per KV tile: the top barrier
// already proves compute(kt-1) is done everywhere, so load(kt+1) can be issued
// right after it (same-parity buffer WAR-safe) and the bottom barrier is gone.
#define FA_BM 128
#define FA_BN 64
#define FA_PADH 72
#define FA_ROWB (FA_PADH * 2)          // 144
#define FA_KV_B (FA_BN * FA_ROWB)      // 9216
#define FA_Q_B  (FA_BM * FA_ROWB)      // 18432
#define FA_DYN  (FA_Q_B + 4 * FA_KV_B) // 55296

__global__ __launch_bounds__(128, 2)
void fa_kernel(const __half* __restrict__ Qh, const __half* __restrict__ Kh,
               const __half* __restrict__ Vh, __half* __restrict__ Oh) {
    extern __shared__ char fsm[];
    const uint32_t sQu = smem_u32(fsm);
    const uint32_t sKu = sQu + FA_Q_B;
    const uint32_t sVu = sKu + 2 * FA_KV_B;
    __half* sQ = (__half*)fsm;

    const int t = threadIdx.x, lane = t & 31, w = t >> 5;
    const int h = blockIdx.y, b = blockIdx.z;
    const size_t qrow0 = (size_t)b * SEQ + (size_t)blockIdx.x * FA_BM;
    const size_t krow0 = (size_t)b * SEQ;
    const int hd = h * DHEAD;

    auto load_kv = [&](int kt, int s) {
#pragma unroll
        for (int i = 0; i < 4; i++) {
            int idx = t + i * 128;
            int r = idx >> 3, c = idx & 7;
            uint32_t so = (uint32_t)(s * FA_KV_B + r * FA_ROWB + c * 16);
            size_t g = (krow0 + (size_t)kt * FA_BN + r) * DMODEL + hd + c * 8;
            cpa16(sKu + so, Kh + g);
            cpa16(sVu + so, Vh + g);
        }
        cpa_commit();
    };

    load_kv(0, 0);
    for (int i = t; i < FA_BM * 8; i += 128) {
        int r = i >> 3, c = i & 7;
        *(uint4*)&sQ[r * FA_PADH + c * 8] =
            *(const uint4*)&Qh[(qrow0 + r) * DMODEL + hd + c * 8];
    }
    __syncthreads();

    uint32_t qa[2][4][4];
#pragma unroll
    for (int mt = 0; mt < 2; mt++) {
        uint32_t rb = sQu + (uint32_t)((w * 32 + mt * 16 + (lane & 15)) * FA_ROWB
                                       + ((lane >> 4) & 1) * 16);
#pragma unroll
        for (int ks = 0; ks < 4; ks++)
            ldsm_x4(qa[mt][ks][0], qa[mt][ks][1], qa[mt][ks][2], qa[mt][ks][3],
                    rb + ks * 32);
    }

    float oacc[2][8][4];
#pragma unroll
    for (int mt = 0; mt < 2; mt++)
#pragma unroll
        for (int j = 0; j < 8; j++)
#pragma unroll
            for (int r = 0; r < 4; r++) oacc[mt][j][r] = 0.f;
    float mrow[2][2] = {{-1e30f, -1e30f}, {-1e30f, -1e30f}};
    float lrow[2][2] = {{0.f, 0.f}, {0.f, 0.f}};

    const uint32_t k_off = (uint32_t)(((lane & 7) + ((lane >> 4) & 1) * 8) * FA_ROWB
                                      + ((lane >> 3) & 1) * 16);
    const uint32_t v_off = (uint32_t)((lane & 15) * FA_ROWB + ((lane >> 4) & 1) * 16);

    const int NT = SEQ / FA_BN;   // 32
#pragma unroll 1
    for (int kt = 0; kt < NT; kt++) {
        asm volatile("cp.async.wait_group 0;" ::: "memory");  // only load kt in flight
        __syncthreads();            // data visible; all warps past compute kt-1

        if (kt + 1 < NT) load_kv(kt + 1, (kt + 1) & 1);

        const uint32_t kb_ = sKu + (uint32_t)(kt & 1) * FA_KV_B;
        const uint32_t vb_ = sVu + (uint32_t)(kt & 1) * FA_KV_B;

#pragma unroll
        for (int mt = 0; mt < 2; mt++) {
            // ---- S = Q K^T (log2e * scale pre-folded into Q) ----
            float sacc[8][4];
#pragma unroll
            for (int j = 0; j < 8; j++)
#pragma unroll
                for (int r = 0; r < 4; r++) sacc[j][r] = 0.f;
#pragma unroll
            for (int ks = 0; ks < 4; ks++)
#pragma unroll
                for (int np = 0; np < 4; np++) {
                    uint32_t kb[4];
                    ldsm_x4(kb[0], kb[1], kb[2], kb[3],
                            kb_ + k_off + (uint32_t)(np * 16 * FA_ROWB + ks * 32));
                    mma_f16(sacc[np * 2 + 0], qa[mt][ks], &kb[0]);
                    mma_f16(sacc[np * 2 + 1], qa[mt][ks], &kb[2]);
                }

            // ---- online softmax (base-2) ----
            float mx0 = -1e30f, mx1 = -1e30f;
#pragma unroll
            for (int j = 0; j < 8; j++) {
                mx0 = fmaxf(mx0, fmaxf(sacc[j][0], sacc[j][1]));
                mx1 = fmaxf(mx1, fmaxf(sacc[j][2], sacc[j][3]));
            }
            mx0 = fmaxf(mx0, __shfl_xor_sync(0xFFFFFFFFu, mx0, 1));
            mx0 = fmaxf(mx0, __shfl_xor_sync(0xFFFFFFFFu, mx0, 2));
            mx1 = fmaxf(mx1, __shfl_xor_sync(0xFFFFFFFFu, mx1, 1));
            mx1 = fmaxf(mx1, __shfl_xor_sync(0xFFFFFFFFu, mx1, 2));
            float mn0 = fmaxf(mrow[mt][0], mx0), mn1 = fmaxf(mrow[mt][1], mx1);
            float c0 = exp2f(mrow[mt][0] - mn0), c1 = exp2f(mrow[mt][1] - mn1);
            float rs0 = 0.f, rs1 = 0.f;
#pragma unroll
            for (int j = 0; j < 8; j++) {
                sacc[j][0] = exp2f(sacc[j][0] - mn0);
                sacc[j][1] = exp2f(sacc[j][1] - mn0);
                sacc[j][2] = exp2f(sacc[j][2] - mn1);
                sacc[j][3] = exp2f(sacc[j][3] - mn1);
                rs0 += sacc[j][0] + sacc[j][1];
                rs1 += sacc[j][2] + sacc[j][3];
            }
            rs0 += __shfl_xor_sync(0xFFFFFFFFu, rs0, 1);
            rs0 += __shfl_xor_sync(0xFFFFFFFFu, rs0, 2);
            rs1 += __shfl_xor_sync(0xFFFFFFFFu, rs1, 1);
            rs1 += __shfl_xor_sync(0xFFFFFFFFu, rs1, 2);
            lrow[mt][0] = lrow[mt][0] * c0 + rs0;
            lrow[mt][1] = lrow[mt][1] * c1 + rs1;
            mrow[mt][0] = mn0; mrow[mt][1] = mn1;
#pragma unroll
            for (int j = 0; j < 8; j++) {
                oacc[mt][j][0] *= c0; oacc[mt][j][1] *= c0;
                oacc[mt][j][2] *= c1; oacc[mt][j][3] *= c1;
            }

            // ---- pack P ----
            uint32_t pa[4][4];
#pragma unroll
            for (int ks = 0; ks < 4; ks++) {
                pa[ks][0] = packh2(sacc[2 * ks][1],     sacc[2 * ks][0]);
                pa[ks][1] = packh2(sacc[2 * ks][3],     sacc[2 * ks][2]);
                pa[ks][2] = packh2(sacc[2 * ks + 1][1], sacc[2 * ks + 1][0]);
                pa[ks][3] = packh2(sacc[2 * ks + 1][3], sacc[2 * ks + 1][2]);
            }

            // ---- O += P V ----
#pragma unroll
            for (int ks = 0; ks < 4; ks++)
#pragma unroll
                for (int np = 0; np < 4; np++) {
                    uint32_t vb[4];
                    ldsm_x4t(vb[0], vb[1], vb[2], vb[3],
                             vb_ + v_off + (uint32_t)(ks * 16 * FA_ROWB + np * 32));
                    mma_f16(oacc[mt][np * 2 + 0], pa[ks], &vb[0]);
                    mma_f16(oacc[mt][np * 2 + 1], pa[ks], &vb[2]);
                }
        }
    }

    // ---- epilogue: normalize, store fp16 ----
#pragma unroll
    for (int mt = 0; mt < 2; mt++) {
        const float il0 = 1.f / lrow[mt][0], il1 = 1.f / lrow[mt][1];
        const size_t r0g = qrow0 + w * 32 + mt * 16 + (lane >> 2);
        const int colb = hd + (lane & 3) * 2;
#pragma unroll
        for (int j = 0; j < 8; j++) {
            const int col = colb + j * 8;
            *(uint32_t*)&Oh[r0g * DMODEL + col] =
                packh2(oacc[mt][j][1] * il0, oacc[mt][j][0] * il0);
            *(uint32_t*)&Oh[(r0g + 8) * DMODEL + col] =
                packh2(oacc[mt][j][3] * il1, oacc[mt][j][2] * il1);
        }
    }
}

// -------------------- launch --------------------
extern "C" void kernel_launch(void* const* d_in, const int* in_sizes, int n_in,
                              void* d_out, int out_size) {
    // metadata order: v, k, q, wq, bq, wk, bk, wv, bv, wo, bo
    const float* v  = (const float*)d_in[0];
    const float* k  = (const float*)d_in[1];
    const float* q  = (const float*)d_in[2];
    const float* wq = (const float*)d_in[3];
    const float* bq = (const float*)d_in[4];
    const float* wk = (const float*)d_in[5];
    const float* bk = (const float*)d_in[6];
    const float* wv = (const float*)d_in[7];
    const float* bv = (const float*)d_in[8];
    const float* wo = (const float*)d_in[9];
    const float* bo = (const float*)d_in[10];
    float* out = (float*)d_out;

    __half *Aq, *Ak, *Av, *Qh, *Kh, *Vh, *Wq, *Wk, *Wv, *Wo;
    cudaGetSymbolAddress((void**)&Aq, g_Aq);
    cudaGetSymbolAddress((void**)&Ak, g_Ak);
    cudaGetSymbolAddress((void**)&Av, g_Av);
    cudaGetSymbolAddress((void**)&Qh, g_Qh);
    cudaGetSymbolAddress((void**)&Kh, g_Kh);
    cudaGetSymbolAddress((void**)&Vh, g_Vh);
    cudaGetSymbolAddress((void**)&Wq, g_Wq);
    cudaGetSymbolAddress((void**)&Wk, g_Wk);
    cudaGetSymbolAddress((void**)&Wv, g_Wv);
    cudaGetSymbolAddress((void**)&Wo, g_Wo);

    cudaFuncSetAttribute(gemm_f16_kernel,
                         cudaFuncAttributeMaxDynamicSharedMemorySize, HGEMM_DYN);
    cudaFuncSetAttribute(gemm_out_kernel,
                         cudaFuncAttributeMaxDynamicSharedMemorySize, HGEMM_DYN);
    cudaFuncSetAttribute(fa_kernel,
                         cudaFuncAttributeMaxDynamicSharedMemorySize, FA_DYN);

    const int N4 = MROWS * DMODEL / 4;     // activation float4s
    const int W4 = DMODEL * DMODEL / 4;    // weight float4s
    const dim3 ggrid(DMODEL / 128, MROWS / 128);   // (8, 64)

    // 1) conversions (R11 structure: dense separate launches)
    conv_f16_kernel<<<(N4 + 255) / 256, 256>>>(q, Aq, N4);
    conv_f16_kernel<<<(W4 + 255) / 256, 256>>>(wq, Wq, W4);
    gemm_f16_kernel<<<ggrid, 256, HGEMM_DYN>>>(Aq, Wq, bq, QSCALE, Qh);

    conv_f16_kernel<<<(N4 + 255) / 256, 256>>>(k, Ak, N4);
    conv_f16_kernel<<<(W4 + 255) / 256, 256>>>(wk, Wk, W4);
    gemm_f16_kernel<<<ggrid, 256, HGEMM_DYN>>>(Ak, Wk, bk, 1.0f, Kh);

    conv_f16_kernel<<<(N4 + 255) / 256, 256>>>(v, Av, N4);
    conv_f16_kernel<<<(W4 + 255) / 256, 256>>>(wv, Wv, W4);
    gemm_f16_kernel<<<ggrid, 256, HGEMM_DYN>>>(Av, Wv, bv, 1.0f, Vh);

    // 2) attention -> fp16 (into Aq, free now)
    fa_kernel<<<dim3(SEQ / FA_BM, NHEADS, BATCH), 128, FA_DYN>>>(Qh, Kh, Vh, Aq);

    // 3) out = O @ wo + bo (fp32)
    conv_f16_kernel<<<(W4 + 255) / 256, 256>>>(wo, Wo, W4);
    gemm_out_kernel<<<ggrid, 256, HGEMM_DYN>>>(Aq, Wo, bo, out);
}